// round 2
// baseline (speedup 1.0000x reference)
#include <cuda_runtime.h>
#include <math.h>

#define NL 16
#define NT 2048
#define ND 2048
#define NR 128
#define NK 1024   // top-k capacity (T * 0.5)

// Scratch (no device allocation allowed -> __device__ globals)
__device__ float g_probs[NL * NT];
__device__ int   g_order[NL * NT];   // g_order[l*NT + rank] = token ; rank<NK -> s2 copy, else gemm

// ---------------------------------------------------------------------------
// Router: probs[l,t] = sigmoid( relu(hidden[l,t,:] @ W_r1[l] + b_r1[l]) @ W_r2[l] + b_r2[l] )
// Block: 256 threads handle 64 tokens of one layer. 4 threads per token,
// each owning 32 of the 128 R-dims (interleaved float4 blocks: r = lane4*4 + j*16 + k).
// ---------------------------------------------------------------------------
__global__ __launch_bounds__(256) void router_kernel(
    const float* __restrict__ hidden,
    const float* __restrict__ W_r1,
    const float* __restrict__ b_r1,
    const float* __restrict__ W_r2,
    const float* __restrict__ b_r2)
{
    __shared__ float sW[32][NR];     // 32 d x 128 r   (16 KB)
    __shared__ float sH[64][33];     // 64 tokens x 32 d, padded
    __shared__ float sB1[NR];
    __shared__ float sW2[NR];

    const int l  = blockIdx.x >> 5;          // / (NT/64) = /32
    const int t0 = (blockIdx.x & 31) * 64;
    const int tid = threadIdx.x;

    if (tid < NR) {
        sB1[tid] = b_r1[l * NR + tid];
        sW2[tid] = W_r2[l * NR + tid];
    }

    const int tok   = tid >> 2;     // 0..63
    const int lane4 = tid & 3;      // r block selector

    float acc[32];
    #pragma unroll
    for (int i = 0; i < 32; i++) acc[i] = 0.f;

    const float* hbase = hidden + ((size_t)l * NT + t0) * ND;
    const float* wbase = W_r1 + (size_t)l * ND * NR;

    for (int d0 = 0; d0 < ND; d0 += 32) {
        // hidden tile: 64x32 floats = 512 float4, 2 per thread (coalesced)
        #pragma unroll
        for (int j = 0; j < 2; j++) {
            int e   = tid + j * 256;         // 0..511
            int row = e >> 3;                // 8 float4 per row
            int c4  = (e & 7) * 4;
            float4 v = *(const float4*)(hbase + (size_t)row * ND + d0 + c4);
            sH[row][c4 + 0] = v.x; sH[row][c4 + 1] = v.y;
            sH[row][c4 + 2] = v.z; sH[row][c4 + 3] = v.w;
        }
        // W_r1 tile: 32x128 floats = 1024 float4, 4 per thread (coalesced)
        #pragma unroll
        for (int j = 0; j < 4; j++) {
            int e  = tid + j * 256;          // 0..1023
            int dd = e >> 5;                 // 32 float4 per row
            int c4 = (e & 31) * 4;
            float4 v = *(const float4*)(wbase + (size_t)(d0 + dd) * NR + c4);
            *(float4*)&sW[dd][c4] = v;
        }
        __syncthreads();

        #pragma unroll
        for (int dd = 0; dd < 32; dd++) {
            float x = sH[tok][dd];
            #pragma unroll
            for (int j = 0; j < 8; j++) {
                float4 w = *(const float4*)&sW[dd][lane4 * 4 + j * 16];
                acc[j * 4 + 0] += x * w.x;
                acc[j * 4 + 1] += x * w.y;
                acc[j * 4 + 2] += x * w.z;
                acc[j * 4 + 3] += x * w.w;
            }
        }
        __syncthreads();
    }

    // relu + dot with W_r2 over this thread's 32 r-values
    float part = 0.f;
    #pragma unroll
    for (int j = 0; j < 8; j++) {
        #pragma unroll
        for (int k = 0; k < 4; k++) {
            int r = lane4 * 4 + j * 16 + k;
            float h = acc[j * 4 + k] + sB1[r];
            h = fmaxf(h, 0.f);
            part += h * sW2[r];
        }
    }
    // reduce across the 4 threads of this token (consecutive lanes)
    part += __shfl_down_sync(0xffffffffu, part, 2, 4);
    part += __shfl_down_sync(0xffffffffu, part, 1, 4);
    if (lane4 == 0) {
        float logit = part + b_r2[l];
        g_probs[l * NT + t0 + tok] = 1.0f / (1.0f + expf(-logit));
    }
}

// ---------------------------------------------------------------------------
// Top-K via exhaustive rank (strict total order -> unique rank -> no atomics).
// One block per layer, 1024 threads, 2 tokens each.
// ---------------------------------------------------------------------------
__global__ __launch_bounds__(1024) void topk_kernel()
{
    __shared__ float sp[NT];
    const int l = blockIdx.x;
    for (int i = threadIdx.x; i < NT; i += 1024) sp[i] = g_probs[l * NT + i];
    __syncthreads();

    #pragma unroll
    for (int ii = 0; ii < 2; ii++) {
        int t = threadIdx.x + ii * 1024;
        float p = sp[t];
        int rank = 0;
        #pragma unroll 4
        for (int j = 0; j < NT; j++) {
            float q = sp[j];
            rank += (q > p) || (q == p && j < t);
        }
        g_order[l * NT + rank] = t;
    }
}

// ---------------------------------------------------------------------------
// Copy s2 rows for selected (top-K) tokens. One block per row.
// ---------------------------------------------------------------------------
__global__ __launch_bounds__(128) void copy_kernel(
    const float* __restrict__ s2, float* __restrict__ out)
{
    const int l = blockIdx.x >> 10;       // / NK
    const int i = blockIdx.x & (NK - 1);
    const int t = g_order[l * NT + i];
    const float4* src = (const float4*)(s2 + ((size_t)l * NT + t) * ND);
    float4*       dst = (float4*)(out + ((size_t)l * NT + t) * ND);
    #pragma unroll
    for (int j = threadIdx.x; j < ND / 4; j += 128) dst[j] = src[j];
}

// ---------------------------------------------------------------------------
// s1 GEMM over the 1024 non-selected tokens per layer:
// out[l, tok, :] = hidden[l, tok, :] @ W_s1[l] + b_s1[l]
// 128x128 tile, BK=8, 256 threads, 8x8 register tile (split 4+4 at +64 to
// keep LDS.128 reads contiguous / conflict-free).
// ---------------------------------------------------------------------------
__global__ __launch_bounds__(256) void s1_gemm_kernel(
    const float* __restrict__ hidden,
    const float* __restrict__ W_s1,
    const float* __restrict__ b_s1,
    float* __restrict__ out)
{
    __shared__ float As[8][128];
    __shared__ float Bs[8][128];
    __shared__ int   rows[128];

    const int l   = blockIdx.z;
    const int n0  = blockIdx.x * 128;
    const int r0  = blockIdx.y * 128;
    const int tid = threadIdx.x;

    if (tid < 128) rows[tid] = g_order[l * NT + NK + r0 + tid];
    __syncthreads();

    const float* hb = hidden + (size_t)l * NT * ND;
    const float* wb = W_s1 + (size_t)l * ND * ND;

    const int arow = tid >> 1;            // 0..127
    const int ak   = (tid & 1) * 4;       // 0 or 4
    const size_t aoff = (size_t)rows[arow] * ND + ak;

    const int brow = tid >> 5;            // 0..7
    const int bn   = (tid & 31) * 4;

    const int cr = (tid >> 4) * 4;        // row base (0..60)
    const int cc = (tid & 15) * 4;        // col base (0..60)

    float acc[8][8];
    #pragma unroll
    for (int i = 0; i < 8; i++)
        #pragma unroll
        for (int j = 0; j < 8; j++) acc[i][j] = 0.f;

    for (int k0 = 0; k0 < ND; k0 += 8) {
        float4 av = *(const float4*)(hb + aoff + k0);
        float4 bv = *(const float4*)(wb + (size_t)(k0 + brow) * ND + n0 + bn);
        As[ak + 0][arow] = av.x; As[ak + 1][arow] = av.y;
        As[ak + 2][arow] = av.z; As[ak + 3][arow] = av.w;
        *(float4*)&Bs[brow][bn] = bv;
        __syncthreads();

        #pragma unroll
        for (int kk = 0; kk < 8; kk++) {
            float a[8], b[8];
            *(float4*)&a[0] = *(const float4*)&As[kk][cr];
            *(float4*)&a[4] = *(const float4*)&As[kk][cr + 64];
            *(float4*)&b[0] = *(const float4*)&Bs[kk][cc];
            *(float4*)&b[4] = *(const float4*)&Bs[kk][cc + 64];
            #pragma unroll
            for (int i = 0; i < 8; i++)
                #pragma unroll
                for (int j = 0; j < 8; j++)
                    acc[i][j] += a[i] * b[j];
        }
        __syncthreads();
    }

    float bias[8];
    #pragma unroll
    for (int jo = 0; jo < 2; jo++)
        #pragma unroll
        for (int jj = 0; jj < 4; jj++)
            bias[jo * 4 + jj] = b_s1[l * ND + n0 + cc + jo * 64 + jj];

    #pragma unroll
    for (int io = 0; io < 2; io++) {
        #pragma unroll
        for (int ii = 0; ii < 4; ii++) {
            int r = cr + io * 64 + ii;
            float* orow = out + ((size_t)l * NT + rows[r]) * ND + n0;
            #pragma unroll
            for (int jo = 0; jo < 2; jo++) {
                float4 v;
                v.x = acc[io * 4 + ii][jo * 4 + 0] + bias[jo * 4 + 0];
                v.y = acc[io * 4 + ii][jo * 4 + 1] + bias[jo * 4 + 1];
                v.z = acc[io * 4 + ii][jo * 4 + 2] + bias[jo * 4 + 2];
                v.w = acc[io * 4 + ii][jo * 4 + 3] + bias[jo * 4 + 3];
                *(float4*)(orow + cc + jo * 64) = v;
            }
        }
    }
}

// ---------------------------------------------------------------------------
extern "C" void kernel_launch(void* const* d_in, const int* in_sizes, int n_in,
                              void* d_out, int out_size)
{
    const float* hidden = (const float*)d_in[0];
    const float* s2     = (const float*)d_in[1];
    const float* W_r1   = (const float*)d_in[2];
    const float* b_r1   = (const float*)d_in[3];
    const float* W_r2   = (const float*)d_in[4];
    const float* b_r2   = (const float*)d_in[5];
    const float* W_s1   = (const float*)d_in[6];
    const float* b_s1   = (const float*)d_in[7];
    float* out = (float*)d_out;

    router_kernel<<<NL * (NT / 64), 256>>>(hidden, W_r1, b_r1, W_r2, b_r2);
    topk_kernel<<<NL, 1024>>>();
    copy_kernel<<<NL * NK, 128>>>(s2, out);
    dim3 g(ND / 128, (NT - NK) / 128, NL);
    s1_gemm_kernel<<<g, 256>>>(hidden, W_s1, b_s1, out);
}

// round 5
// speedup vs baseline: 1.3853x; 1.3853x over previous
#include <cuda_runtime.h>
#include <cuda_bf16.h>
#include <math.h>
#include <stdint.h>

#define NL 16
#define NT 2048
#define ND 2048
#define NR 128
#define NK 1024   // top-k capacity (T * 0.5)

// Scratch (no device allocation allowed -> __device__ globals)
__device__ float g_probs[NL * NT];
__device__ int   g_order[NL * NT];   // g_order[l*NT + rank] = token ; rank<NK -> s2 copy, else gemm

// ===========================================================================
// Helpers (sm_80-compatible PTX only: ldmatrix + mma.sync)
// ===========================================================================
__device__ __forceinline__ uint32_t smem_u32(const void* p) {
    uint32_t a;
    asm("{ .reg .u64 t; cvta.to.shared.u64 t, %1; cvt.u32.u64 %0, t; }" : "=r"(a) : "l"(p));
    return a;
}
__device__ __forceinline__ void ldsm_x4(uint32_t* d, uint32_t addr) {
    asm volatile("ldmatrix.sync.aligned.m8n8.x4.shared.b16 {%0,%1,%2,%3}, [%4];"
                 : "=r"(d[0]), "=r"(d[1]), "=r"(d[2]), "=r"(d[3]) : "r"(addr));
}
__device__ __forceinline__ void mma_bf16(float* c, const uint32_t* a, uint32_t b0, uint32_t b1) {
    asm volatile(
        "mma.sync.aligned.m16n8k16.row.col.f32.bf16.bf16.f32 "
        "{%0,%1,%2,%3}, {%4,%5,%6,%7}, {%8,%9}, {%0,%1,%2,%3};"
        : "+f"(c[0]), "+f"(c[1]), "+f"(c[2]), "+f"(c[3])
        : "r"(a[0]), "r"(a[1]), "r"(a[2]), "r"(a[3]), "r"(b0), "r"(b1));
}
// Dekker split of two fp32 -> packed bf16 hi word + lo word (low half = first elem)
__device__ __forceinline__ void split2(float x, float y, uint32_t& h, uint32_t& l) {
    __nv_bfloat16 hx = __float2bfloat16_rn(x);
    __nv_bfloat16 hy = __float2bfloat16_rn(y);
    __nv_bfloat16 lx = __float2bfloat16_rn(x - __bfloat162float(hx));
    __nv_bfloat16 ly = __float2bfloat16_rn(y - __bfloat162float(hy));
    __nv_bfloat162 th = __halves2bfloat162(hx, hy);
    __nv_bfloat162 tl = __halves2bfloat162(lx, ly);
    h = *reinterpret_cast<uint32_t*>(&th);
    l = *reinterpret_cast<uint32_t*>(&tl);
}

// ---------------------------------------------------------------------------
// Router (proven in R1)
// ---------------------------------------------------------------------------
__global__ __launch_bounds__(256) void router_kernel(
    const float* __restrict__ hidden,
    const float* __restrict__ W_r1,
    const float* __restrict__ b_r1,
    const float* __restrict__ W_r2,
    const float* __restrict__ b_r2)
{
    __shared__ float sW[32][NR];
    __shared__ float sH[64][33];
    __shared__ float sB1[NR];
    __shared__ float sW2[NR];

    const int l  = blockIdx.x >> 5;
    const int t0 = (blockIdx.x & 31) * 64;
    const int tid = threadIdx.x;

    if (tid < NR) {
        sB1[tid] = b_r1[l * NR + tid];
        sW2[tid] = W_r2[l * NR + tid];
    }

    const int tok   = tid >> 2;
    const int lane4 = tid & 3;

    float acc[32];
    #pragma unroll
    for (int i = 0; i < 32; i++) acc[i] = 0.f;

    const float* hbase = hidden + ((size_t)l * NT + t0) * ND;
    const float* wbase = W_r1 + (size_t)l * ND * NR;

    for (int d0 = 0; d0 < ND; d0 += 32) {
        #pragma unroll
        for (int j = 0; j < 2; j++) {
            int e   = tid + j * 256;
            int row = e >> 3;
            int c4  = (e & 7) * 4;
            float4 v = *(const float4*)(hbase + (size_t)row * ND + d0 + c4);
            sH[row][c4 + 0] = v.x; sH[row][c4 + 1] = v.y;
            sH[row][c4 + 2] = v.z; sH[row][c4 + 3] = v.w;
        }
        #pragma unroll
        for (int j = 0; j < 4; j++) {
            int e  = tid + j * 256;
            int dd = e >> 5;
            int c4 = (e & 31) * 4;
            float4 v = *(const float4*)(wbase + (size_t)(d0 + dd) * NR + c4);
            *(float4*)&sW[dd][c4] = v;
        }
        __syncthreads();

        #pragma unroll
        for (int dd = 0; dd < 32; dd++) {
            float x = sH[tok][dd];
            #pragma unroll
            for (int j = 0; j < 8; j++) {
                float4 w = *(const float4*)&sW[dd][lane4 * 4 + j * 16];
                acc[j * 4 + 0] += x * w.x;
                acc[j * 4 + 1] += x * w.y;
                acc[j * 4 + 2] += x * w.z;
                acc[j * 4 + 3] += x * w.w;
            }
        }
        __syncthreads();
    }

    float part = 0.f;
    #pragma unroll
    for (int j = 0; j < 8; j++) {
        #pragma unroll
        for (int k = 0; k < 4; k++) {
            int r = lane4 * 4 + j * 16 + k;
            float h = acc[j * 4 + k] + sB1[r];
            h = fmaxf(h, 0.f);
            part += h * sW2[r];
        }
    }
    part += __shfl_down_sync(0xffffffffu, part, 2, 4);
    part += __shfl_down_sync(0xffffffffu, part, 1, 4);
    if (lane4 == 0) {
        float logit = part + b_r2[l];
        g_probs[l * NT + t0 + tok] = 1.0f / (1.0f + expf(-logit));
    }
}

// ---------------------------------------------------------------------------
// Top-K via exhaustive rank (proven)
// ---------------------------------------------------------------------------
__global__ __launch_bounds__(1024) void topk_kernel()
{
    __shared__ float sp[NT];
    const int l = blockIdx.x;
    for (int i = threadIdx.x; i < NT; i += 1024) sp[i] = g_probs[l * NT + i];
    __syncthreads();

    #pragma unroll
    for (int ii = 0; ii < 2; ii++) {
        int t = threadIdx.x + ii * 1024;
        float p = sp[t];
        int rank = 0;
        #pragma unroll 4
        for (int j = 0; j < NT; j++) {
            float q = sp[j];
            rank += (q > p) || (q == p && j < t);
        }
        g_order[l * NT + rank] = t;
    }
}

// ---------------------------------------------------------------------------
// Copy s2 rows (proven)
// ---------------------------------------------------------------------------
__global__ __launch_bounds__(128) void copy_kernel(
    const float* __restrict__ s2, float* __restrict__ out)
{
    const int l = blockIdx.x >> 10;
    const int i = blockIdx.x & (NK - 1);
    const int t = g_order[l * NT + i];
    const float4* src = (const float4*)(s2 + ((size_t)l * NT + t) * ND);
    float4*       dst = (float4*)(out + ((size_t)l * NT + t) * ND);
    #pragma unroll
    for (int j = threadIdx.x; j < ND / 4; j += 128) dst[j] = src[j];
}

// ---------------------------------------------------------------------------
// s1 GEMM with HMMA (mma.sync bf16), fp32 via hi/lo Dekker split (3 products).
// CTA tile 128(M, gathered) x 128(N), K-chunk 32, double-buffered smem.
// smem arrays (bf16, row stride 40 elems = 80B, pad kills LDSM/STS conflicts):
//   Ah[128][40] Al[128][40] Bh[128][40] Bl[128][40]   per buffer (40960 B)
// 8 warps: warp grid 2(m) x 4(n) -> warp tile 64 x 32.
// ---------------------------------------------------------------------------
#define KC       32
#define ASTRIDE  40
#define OFF_AL   10240
#define OFF_BH   20480
#define OFF_BL   30720
#define BUFB     40960
#define SM_ROWS  81920
#define SM_TOTAL 82432

__global__ __launch_bounds__(256, 1) void s1_gemm_mma(
    const float* __restrict__ hidden,
    const float* __restrict__ W_s1,
    const float* __restrict__ b_s1,
    float* __restrict__ out)
{
    extern __shared__ char sm[];
    const int l   = blockIdx.z;
    const int n0  = blockIdx.x * 128;
    const int r0  = blockIdx.y * 128;
    const int tid = threadIdx.x;
    const int w   = tid >> 5;
    const int lane = tid & 31;

    int* srows = (int*)(sm + SM_ROWS);
    if (tid < 128) srows[tid] = g_order[l * NT + NK + r0 + tid];
    __syncthreads();

    const float* hb = hidden + (size_t)l * NT * ND;
    const float* wb = W_s1 + (size_t)l * ND * ND;

    // loader assignment: thread -> (index r in 0..127, k-half kh in {0,16})
    const int r  = tid >> 1;
    const int kh = (tid & 1) * 16;
    const float* arow_p = hb + (size_t)srows[r] * ND + kh;   // A row r, k offset kh
    const float* bcol_p = wb + n0 + r;                       // B column n=r
    const uint32_t sts_off = (uint32_t)(r * ASTRIDE + kh) * 2;

    const uint32_t sbase = smem_u32(sm);

    const int wm = w & 1, wn = w >> 1;
    const int m_base = wm * 64, n_base = wn * 32;

    float acc[4][4][4];
    #pragma unroll
    for (int i = 0; i < 4; i++)
        #pragma unroll
        for (int g = 0; g < 4; g++)
            #pragma unroll
            for (int e = 0; e < 4; e++) acc[i][g][e] = 0.f;

    float4 av[4];
    float  bv[16];

    #define LOAD_CHUNK(c) do {                                                  \
        const int kk0 = (c) * KC;                                               \
        _Pragma("unroll")                                                       \
        for (int j = 0; j < 4; j++) av[j] = *(const float4*)(arow_p + kk0 + j * 4); \
        _Pragma("unroll")                                                       \
        for (int i = 0; i < 16; i++) bv[i] = __ldg(bcol_p + (size_t)(kk0 + kh + i) * ND); \
    } while (0)

    #define STORE_CHUNK(buf) do {                                               \
        char* base = sm + (buf) * BUFB;                                         \
        uint32_t hw[8], lw[8];                                                  \
        _Pragma("unroll")                                                       \
        for (int j = 0; j < 4; j++) {                                           \
            split2(av[j].x, av[j].y, hw[2*j],   lw[2*j]);                       \
            split2(av[j].z, av[j].w, hw[2*j+1], lw[2*j+1]);                     \
        }                                                                       \
        *(uint4*)(base + sts_off)               = make_uint4(hw[0],hw[1],hw[2],hw[3]); \
        *(uint4*)(base + sts_off + 16)          = make_uint4(hw[4],hw[5],hw[6],hw[7]); \
        *(uint4*)(base + OFF_AL + sts_off)      = make_uint4(lw[0],lw[1],lw[2],lw[3]); \
        *(uint4*)(base + OFF_AL + sts_off + 16) = make_uint4(lw[4],lw[5],lw[6],lw[7]); \
        _Pragma("unroll")                                                       \
        for (int i = 0; i < 8; i++) split2(bv[2*i], bv[2*i+1], hw[i], lw[i]);   \
        *(uint4*)(base + OFF_BH + sts_off)      = make_uint4(hw[0],hw[1],hw[2],hw[3]); \
        *(uint4*)(base + OFF_BH + sts_off + 16) = make_uint4(hw[4],hw[5],hw[6],hw[7]); \
        *(uint4*)(base + OFF_BL + sts_off)      = make_uint4(lw[0],lw[1],lw[2],lw[3]); \
        *(uint4*)(base + OFF_BL + sts_off + 16) = make_uint4(lw[4],lw[5],lw[6],lw[7]); \
    } while (0)

    const int frow = lane & 15;            // ldmatrix lane row
    const int fcol = (lane >> 4) * 8;      // ldmatrix lane col group

    #define COMPUTE_CHUNK(buf) do {                                             \
        const uint32_t bb = sbase + (buf) * BUFB;                               \
        _Pragma("unroll")                                                       \
        for (int s = 0; s < 2; s++) {                                           \
            const int k0 = s * 16;                                              \
            uint32_t ah[4][4], al[4][4], bh[2][4], bl[2][4];                    \
            const uint32_t a_ad = bb + ((m_base + frow) * ASTRIDE + k0 + fcol) * 2; \
            _Pragma("unroll")                                                   \
            for (int i = 0; i < 4; i++) {                                       \
                ldsm_x4(ah[i], a_ad + i * (16 * ASTRIDE * 2));                  \
                ldsm_x4(al[i], a_ad + OFF_AL + i * (16 * ASTRIDE * 2));         \
            }                                                                   \
            const uint32_t b_ad = bb + OFF_BH + ((n_base + frow) * ASTRIDE + k0 + fcol) * 2; \
            _Pragma("unroll")                                                   \
            for (int j = 0; j < 2; j++) {                                       \
                ldsm_x4(bh[j], b_ad + j * (16 * ASTRIDE * 2));                  \
                ldsm_x4(bl[j], b_ad + (OFF_BL - OFF_BH) + j * (16 * ASTRIDE * 2)); \
            }                                                                   \
            _Pragma("unroll")                                                   \
            for (int i = 0; i < 4; i++) {                                       \
                _Pragma("unroll")                                               \
                for (int jj = 0; jj < 2; jj++) {                                \
                    _Pragma("unroll")                                           \
                    for (int hi = 0; hi < 2; hi++) {                            \
                        const int g = jj * 2 + hi;                              \
                        mma_bf16(acc[i][g], ah[i], bh[jj][hi], bh[jj][hi + 2]); \
                        mma_bf16(acc[i][g], ah[i], bl[jj][hi], bl[jj][hi + 2]); \
                        mma_bf16(acc[i][g], al[i], bh[jj][hi], bh[jj][hi + 2]); \
                    }                                                           \
                }                                                               \
            }                                                                   \
        }                                                                       \
    } while (0)

    LOAD_CHUNK(0);
    STORE_CHUNK(0);
    __syncthreads();

    for (int c = 0; c < ND / KC; c++) {
        if (c < ND / KC - 1) LOAD_CHUNK(c + 1);
        COMPUTE_CHUNK(c & 1);
        __syncthreads();
        if (c < ND / KC - 1) {
            STORE_CHUNK((c + 1) & 1);
            __syncthreads();
        }
    }

    // Epilogue: c-frag (m16n8): c0,c1 @ (row=t/4, col=2(t%4)); c2,c3 @ row+8
    const int tq = lane >> 2;
    const int tr = lane & 3;
    #pragma unroll
    for (int g = 0; g < 4; g++) {
        const int col = n_base + g * 8 + tr * 2;
        const float bx = __ldg(b_s1 + l * ND + n0 + col);
        const float by = __ldg(b_s1 + l * ND + n0 + col + 1);
        #pragma unroll
        for (int i = 0; i < 4; i++) {
            const int rl = m_base + i * 16 + tq;
            float* o0 = out + ((size_t)l * NT + srows[rl])     * ND + n0 + col;
            float* o1 = out + ((size_t)l * NT + srows[rl + 8]) * ND + n0 + col;
            float2 v0 = make_float2(acc[i][g][0] + bx, acc[i][g][1] + by);
            float2 v1 = make_float2(acc[i][g][2] + bx, acc[i][g][3] + by);
            *(float2*)o0 = v0;
            *(float2*)o1 = v1;
        }
    }
}

// ---------------------------------------------------------------------------
extern "C" void kernel_launch(void* const* d_in, const int* in_sizes, int n_in,
                              void* d_out, int out_size)
{
    const float* hidden = (const float*)d_in[0];
    const float* s2     = (const float*)d_in[1];
    const float* W_r1   = (const float*)d_in[2];
    const float* b_r1   = (const float*)d_in[3];
    const float* W_r2   = (const float*)d_in[4];
    const float* b_r2   = (const float*)d_in[5];
    const float* W_s1   = (const float*)d_in[6];
    const float* b_s1   = (const float*)d_in[7];
    float* out = (float*)d_out;

    static bool attr_done = false;
    if (!attr_done) {
        cudaFuncSetAttribute(s1_gemm_mma, cudaFuncAttributeMaxDynamicSharedMemorySize, SM_TOTAL);
        attr_done = true;
    }

    router_kernel<<<NL * (NT / 64), 256>>>(hidden, W_r1, b_r1, W_r2, b_r2);
    topk_kernel<<<NL, 1024>>>();
    copy_kernel<<<NL * NK, 128>>>(s2, out);
    dim3 g(ND / 128, (NT - NK) / 128, NL);
    s1_gemm_mma<<<g, 256, SM_TOTAL>>>(hidden, W_s1, b_s1, out);
}